// round 9
// baseline (speedup 1.0000x reference)
#include <cuda_runtime.h>
#include <cuda_fp16.h>
#include <cstdint>

#define STATE_DIM 512
#define AFEAT 64
#define HID 256
#define HID2 128
#define KACT 1000
#define NROWS 256000
#define TILE_M 64
#define NTILES 4000            // 256000 / 64

__device__ float g_hstate[256 * HID];

__device__ __forceinline__ uint32_t pk(float lo, float hi) {
    __half2 h = __floats2half2_rn(lo, hi);      // low 16 bits = lo
    return *(uint32_t*)&h;
}
__device__ __forceinline__ uint32_t pkr(float lo, float hi) {
    return pk(fmaxf(lo, 0.f), fmaxf(hi, 0.f));
}

// m16n8k16 f16 MMA, f32 accum, C += A*B (row.col)
__device__ __forceinline__ void mma16(float* c, const uint4& a, uint32_t b0, uint32_t b1) {
    asm volatile("mma.sync.aligned.m16n8k16.row.col.f32.f16.f16.f32 "
        "{%0,%1,%2,%3}, {%4,%5,%6,%7}, {%8,%9}, {%0,%1,%2,%3};"
        : "+f"(c[0]), "+f"(c[1]), "+f"(c[2]), "+f"(c[3])
        : "r"(a.x), "r"(a.y), "r"(a.z), "r"(a.w), "r"(b0), "r"(b1));
}

// ---------------------------------------------------------------------------
// hstate: h_state[b][j] = state[b] . W1[:512,j] + b1[j]   (exact fp32)
// ---------------------------------------------------------------------------
__global__ __launch_bounds__(256) void hstate_kernel(
    const float* __restrict__ state,
    const float* __restrict__ W1,
    const float* __restrict__ b1)
{
    __shared__ float s[4 * STATE_DIM];
    const int b0 = blockIdx.x * 4;
    const int t = threadIdx.x;
    for (int i = t; i < 4 * STATE_DIM; i += 256)
        s[i] = state[b0 * STATE_DIM + i];
    __syncthreads();

    float a0, a1, a2, a3;
    a0 = a1 = a2 = a3 = b1[t];
#pragma unroll 8
    for (int k = 0; k < STATE_DIM; k++) {
        float w = W1[k * HID + t];
        a0 = fmaf(s[k], w, a0);
        a1 = fmaf(s[512 + k], w, a1);
        a2 = fmaf(s[1024 + k], w, a2);
        a3 = fmaf(s[1536 + k], w, a3);
    }
    g_hstate[(b0 + 0) * HID + t] = a0;
    g_hstate[(b0 + 1) * HID + t] = a1;
    g_hstate[(b0 + 2) * HID + t] = a2;
    g_hstate[(b0 + 3) * HID + t] = a3;
}

// ---------------------------------------------------------------------------
// Main fused MLP. 512 threads = 16 warps, 4(M)x4(N) grid, TILE_M=64.
// ONE __syncthreads per iteration; pipeline: L1(u) | L2(u-G) | out(u-2G),
// double-buffered sH1f / sHS / sOutP.
//
// B-frag uint4: x=(n8=0,k0..7) y=(n8=0,k8..15) z=(n8=1,k0..7) w=(n8=1,k8..15)
// A-frag uint4: x=(r,k0..) y=(r+8,k0..) z=(r,k8..) w=(r+8,k8..), f16x2 lo=even k
//
// SMEM (float units):
//  sW2f 16384 | sW1f 8192 | sH1f 2x8192 | sHS 2x512 | sB2 128 | sW3 128 | sOutP 2x256
// ---------------------------------------------------------------------------
#define OFF_W2F 0
#define OFF_W1F 16384
#define OFF_H1F 24576
#define OFF_HS  40960
#define OFF_B2  41984
#define OFF_W3  42112
#define OFF_OUT 42240
#define SMEM_FLOATS 42752
#define SMEM_BYTES (SMEM_FLOATS * 4)

__global__ void __launch_bounds__(512, 1) actor_main(
    const float* __restrict__ af, const float* __restrict__ W1,
    const float* __restrict__ W2, const float* __restrict__ b2,
    const float* __restrict__ W3, const float* __restrict__ b3,
    float* __restrict__ out)
{
    extern __shared__ float sm[];
    uint32_t* sW2f = (uint32_t*)(sm + OFF_W2F);
    uint32_t* sW1f = (uint32_t*)(sm + OFF_W1F);
    float* sHS  = sm + OFF_HS;     // [2][512]
    float* sB2  = sm + OFF_B2;
    float* sW3  = sm + OFF_W3;

    const int t = threadIdx.x;
    const int lane = t & 31;
    const int w = t >> 5;
    const int mg = w & 3;          // rows mg*16 .. +15
    const int ng = w >> 2;         // L1: cols ng*64..; L2: cols ng*32..

    // ---- build W2 frags: [ng(4)][ks(16)][np(2)][lane(32)] uint4 ----
    for (int i = t; i < 16384; i += 512) {
        int ws = i & 3, ln = (i >> 2) & 31;
        int np = (i >> 7) & 1, ks = (i >> 8) & 15, g = (i >> 12) & 3;
        int krow = ks * 16 + (ws & 1) * 8 + (ln & 3) * 2;
        int col  = g * 32 + np * 16 + (ws >> 1) * 8 + (ln >> 2);
        sW2f[i] = pk(W2[krow * HID2 + col], W2[(krow + 1) * HID2 + col]);
    }
    // ---- build W1a frags: [ng(4)][ks(4)][np(4)][lane(32)] uint4 ----
    for (int i = t; i < 8192; i += 512) {
        int ws = i & 3, ln = (i >> 2) & 31;
        int np = (i >> 7) & 3, ks = (i >> 9) & 3, g = (i >> 11) & 3;
        int krow = STATE_DIM + ks * 16 + (ws & 1) * 8 + (ln & 3) * 2;
        int col  = g * 64 + np * 16 + (ws >> 1) * 8 + (ln >> 2);
        sW1f[i] = pk(W1[krow * HID + col], W1[(krow + 1) * HID + col]);
    }
    if (t < 128) { sB2[t] = b2[t]; sW3[t] = W3[t]; }

    auto stage_hs = [&](int tl, int buf) {
        int r0 = tl * TILE_M;
        int blo = r0 / KACT;
        int bhi = (r0 + TILE_M - 1) / KACT;
        sHS[buf * 512 + t] = g_hstate[(t < 256 ? blo : bhi) * HID + (t & 255)];
    };

    const int G = gridDim.x;
    const int t0 = blockIdx.x;
    const int kmax = (NTILES - 1 - t0) / G;

    // ---- prologue ----
    stage_hs(t0, 0);
    __syncthreads();

    const float bias3 = __ldg(b3);
    const uint4* w1v = (const uint4*)sW1f;
    const uint4* w2v = (const uint4*)sW2f;
    uint4* h1f = (uint4*)(sm + OFF_H1F);        // [2][4096 u32 = 1024 uint4... per buf 2048 uint4]

    const int a_row = mg * 16 + (lane >> 2);
    const int a_col = (lane & 3) * 2;

    int u = t0;
    for (int it = 0; ; it++, u += G) {
        const int p = it & 1;

        // ---- out(u-2G): reduce 4 ng-slots, written to sOutP[p] last iter ----
        if (it >= 2 && t < 64) {
            float4 v = *(float4*)(sm + OFF_OUT + p * 256 + t * 4);
            out[(u - 2 * G) * TILE_M + t] = v.x + v.y + v.z + v.w + bias3;
        }
        if (it == kmax + 2) break;

        if (u < NTILES) {
            // ---- L1(u): C = af @ W1a, C init = h_state (exact fp32) ----
            // C-frag: bit0 = col parity, bit1 = row+8
            float acc[8][4];
            const float* hsc = sHS + p * 512;
            {
                const int r = mg * 16 + (lane >> 2);
#pragma unroll
                for (int nt = 0; nt < 8; nt++)
#pragma unroll
                for (int rg = 0; rg < 4; rg++) {
                    int rr = r + (rg >> 1) * 8;
                    int c = ng * 64 + nt * 8 + 2 * (lane & 3) + (rg & 1);
                    int split = (u * TILE_M / KACT + 1) * KACT - u * TILE_M;
                    acc[nt][rg] = hsc[(rr >= split ? 256 : 0) + c];
                }
            }
            // A1 frags direct from gmem (hoisted loads)
            float2 av[4][4];
#pragma unroll
            for (int ks = 0; ks < 4; ks++) {
                const float* pA = af + (size_t)(u * TILE_M + a_row) * AFEAT
                                     + ks * 16 + a_col;
                av[ks][0] = *(const float2*)(pA);
                av[ks][1] = *(const float2*)(pA + 8 * AFEAT);
                av[ks][2] = *(const float2*)(pA + 8);
                av[ks][3] = *(const float2*)(pA + 8 * AFEAT + 8);
            }
#pragma unroll
            for (int ks = 0; ks < 4; ks++) {
                uint4 a;
                a.x = pk(av[ks][0].x, av[ks][0].y);
                a.y = pk(av[ks][1].x, av[ks][1].y);
                a.z = pk(av[ks][2].x, av[ks][2].y);
                a.w = pk(av[ks][3].x, av[ks][3].y);
#pragma unroll
                for (int np = 0; np < 4; np++) {
                    uint4 b = w1v[((ng * 4 + ks) * 4 + np) * 32 + lane];
                    mma16(acc[np * 2],     a, b.x, b.y);
                    mma16(acc[np * 2 + 1], a, b.z, b.w);
                }
            }
            // ---- ep1(u): relu -> f16 -> h1f[p] as L2 A-frags ----
#pragma unroll
            for (int q = 0; q < 4; q++) {
                uint4 v;
                v.x = pkr(acc[2 * q][0],     acc[2 * q][1]);
                v.y = pkr(acc[2 * q][2],     acc[2 * q][3]);
                v.z = pkr(acc[2 * q + 1][0], acc[2 * q + 1][1]);
                v.w = pkr(acc[2 * q + 1][2], acc[2 * q + 1][3]);
                h1f[p * 2048 + (mg * 16 + ng * 4 + q) * 32 + lane] = v;
            }
            if (u + G < NTILES) stage_hs(u + G, p ^ 1);
        }

        if (it >= 1 && u - G < NTILES) {
            // ---- L2(u-G): C2 = h1 @ W2 (reads h1f[p^1]) ----
            float acc2[4][4];
#pragma unroll
            for (int nt = 0; nt < 4; nt++)
#pragma unroll
            for (int rg = 0; rg < 4; rg++) acc2[nt][rg] = 0.f;
            const uint4* h1p = h1f + (p ^ 1) * 2048;
#pragma unroll
            for (int ks = 0; ks < 16; ks++) {
                uint4 a = h1p[(mg * 16 + ks) * 32 + lane];
#pragma unroll
                for (int np = 0; np < 2; np++) {
                    uint4 b = w2v[((ng * 16 + ks) * 2 + np) * 32 + lane];
                    mma16(acc2[np * 2],     a, b.x, b.y);
                    mma16(acc2[np * 2 + 1], a, b.z, b.w);
                }
            }
            // ---- L3(u-G): relu(C2+b2).W3 partials -> sOutP[p^1][row][ng] ----
            float part[2] = {0.f, 0.f};
#pragma unroll
            for (int nt = 0; nt < 4; nt++)
#pragma unroll
            for (int rg = 0; rg < 4; rg++) {
                int c = ng * 32 + nt * 8 + 2 * (lane & 3) + (rg & 1);
                float v = fmaxf(acc2[nt][rg] + sB2[c], 0.f);
                part[rg >> 1] += v * sW3[c];
            }
#pragma unroll
            for (int rb = 0; rb < 2; rb++) {
                float v = part[rb];
                v += __shfl_xor_sync(0xffffffffu, v, 1);
                v += __shfl_xor_sync(0xffffffffu, v, 2);
                if ((lane & 3) == 0)
                    sm[OFF_OUT + (p ^ 1) * 256
                       + (mg * 16 + rb * 8 + (lane >> 2)) * 4 + ng] = v;
            }
        }
        __syncthreads();   // the only barrier per iteration
    }
}

// ---------------------------------------------------------------------------
extern "C" void kernel_launch(void* const* d_in, const int* in_sizes, int n_in,
                              void* d_out, int out_size)
{
    const float* state = (const float*)d_in[0];
    const float* afeats = (const float*)d_in[1];
    const float* W1    = (const float*)d_in[2];
    const float* b1    = (const float*)d_in[3];
    const float* W2    = (const float*)d_in[4];
    const float* b2    = (const float*)d_in[5];
    const float* W3    = (const float*)d_in[6];
    const float* b3    = (const float*)d_in[7];
    float* out = (float*)d_out;
    (void)in_sizes; (void)n_in; (void)out_size;

    static int sm_count = 0;
    if (sm_count == 0) {
        cudaDeviceGetAttribute(&sm_count, cudaDevAttrMultiProcessorCount, 0);
        if (sm_count <= 0) sm_count = 148;
        cudaFuncSetAttribute(actor_main,
                             cudaFuncAttributeMaxDynamicSharedMemorySize, SMEM_BYTES);
    }

    hstate_kernel<<<64, 256>>>(state, W1, b1);
    actor_main<<<sm_count, 512, SMEM_BYTES>>>(afeats, W1, W2, b2, W3, b3, out);
}

// round 10
// speedup vs baseline: 1.2513x; 1.2513x over previous
#include <cuda_runtime.h>
#include <cuda_fp16.h>
#include <cstdint>

#define STATE_DIM 512
#define AFEAT 64
#define HID 256
#define HID2 128
#define KACT 1000
#define NROWS 256000
#define TILE_M 128
#define NTILES 2000            // 256000 / 128

__device__ float g_hstate[256 * HID];

__device__ __forceinline__ uint32_t pk(float lo, float hi) {
    __half2 h = __floats2half2_rn(lo, hi);      // low 16 bits = lo
    return *(uint32_t*)&h;
}
__device__ __forceinline__ uint32_t pkr(float lo, float hi) {
    return pk(fmaxf(lo, 0.f), fmaxf(hi, 0.f));
}

// m16n8k16 f16 MMA, f32 accum, C += A*B (row.col)
__device__ __forceinline__ void mma16(float* c, const uint4& a, uint32_t b0, uint32_t b1) {
    asm volatile("mma.sync.aligned.m16n8k16.row.col.f32.f16.f16.f32 "
        "{%0,%1,%2,%3}, {%4,%5,%6,%7}, {%8,%9}, {%0,%1,%2,%3};"
        : "+f"(c[0]), "+f"(c[1]), "+f"(c[2]), "+f"(c[3])
        : "r"(a.x), "r"(a.y), "r"(a.z), "r"(a.w), "r"(b0), "r"(b1));
}

// ---------------------------------------------------------------------------
// hstate: h_state[b][j] = state[b] . W1[:512,j] + b1[j]   (exact fp32)
// ---------------------------------------------------------------------------
__global__ __launch_bounds__(256) void hstate_kernel(
    const float* __restrict__ state,
    const float* __restrict__ W1,
    const float* __restrict__ b1)
{
    __shared__ float s[4 * STATE_DIM];
    const int b0 = blockIdx.x * 4;
    const int t = threadIdx.x;
    for (int i = t; i < 4 * STATE_DIM; i += 256)
        s[i] = state[b0 * STATE_DIM + i];
    __syncthreads();

    float a0, a1, a2, a3;
    a0 = a1 = a2 = a3 = b1[t];
#pragma unroll 8
    for (int k = 0; k < STATE_DIM; k++) {
        float w = W1[k * HID + t];
        a0 = fmaf(s[k], w, a0);
        a1 = fmaf(s[512 + k], w, a1);
        a2 = fmaf(s[1024 + k], w, a2);
        a3 = fmaf(s[1536 + k], w, a3);
    }
    g_hstate[(b0 + 0) * HID + t] = a0;
    g_hstate[(b0 + 1) * HID + t] = a1;
    g_hstate[(b0 + 2) * HID + t] = a2;
    g_hstate[(b0 + 3) * HID + t] = a3;
}

// ---------------------------------------------------------------------------
// Main fused MLP. 512 threads = 16 warps, 4(M)x4(N) grid, TILE_M=128.
// Each warp: 32 rows (2 m16 frags). A1 staged in double-buffered SMEM frags
// (coalesced-ish float2 gmem loads -> pack f16 -> STS.128), prefetched 1 tile.
//
// B-frag uint4: x=(n8=0,k0..7) y=(n8=0,k8..15) z=(n8=1,k0..7) w=(n8=1,k8..15)
// A-frag uint4: x=(r,k0..) y=(r+8,k0..) z=(r,k8..) w=(r+8,k8..), f16x2 lo=even k
//
// SMEM (float units):
//  sW2f 16384 | sW1f 8192 | sH1f 16384 | sAf 2x4096 | sHS 2x512 | sB2/sW3/sOut 384
// ---------------------------------------------------------------------------
#define OFF_W2F 0
#define OFF_W1F 16384
#define OFF_H1F 24576
#define OFF_AF  40960
#define OFF_HS  49152
#define OFF_B2  50176
#define OFF_W3  50304
#define OFF_OUT 50432
#define SMEM_FLOATS 50560
#define SMEM_BYTES (SMEM_FLOATS * 4)

__global__ void __launch_bounds__(512, 1) actor_main(
    const float* __restrict__ af, const float* __restrict__ W1,
    const float* __restrict__ W2, const float* __restrict__ b2,
    const float* __restrict__ W3, const float* __restrict__ b3,
    float* __restrict__ out)
{
    extern __shared__ float sm[];
    uint32_t* sW2f = (uint32_t*)(sm + OFF_W2F);
    uint32_t* sW1f = (uint32_t*)(sm + OFF_W1F);
    uint32_t* sH1f = (uint32_t*)(sm + OFF_H1F);
    uint4*    sAfq = (uint4*)(sm + OFF_AF);      // [2][1024] uint4
    float* sHS  = sm + OFF_HS;     // [2][512]
    float* sB2  = sm + OFF_B2;
    float* sW3  = sm + OFF_W3;
    float* sOut = sm + OFF_OUT;

    const int t = threadIdx.x;
    const int lane = t & 31;
    const int w = t >> 5;
    const int mg = w & 3;          // rows mg*32 .. +31
    const int ng = w >> 2;         // L1: cols ng*64..; L2: cols ng*32..

    // ---- build W2 frags: [ng(4)][ks(16)][np(2)][lane(32)] uint4 ----
    for (int i = t; i < 16384; i += 512) {
        int ws = i & 3, ln = (i >> 2) & 31;
        int np = (i >> 7) & 1, ks = (i >> 8) & 15, g = (i >> 12) & 3;
        int krow = ks * 16 + (ws & 1) * 8 + (ln & 3) * 2;
        int col  = g * 32 + np * 16 + (ws >> 1) * 8 + (ln >> 2);
        sW2f[i] = pk(W2[krow * HID2 + col], W2[(krow + 1) * HID2 + col]);
    }
    // ---- build W1a frags: [ng(4)][ks(4)][np(4)][lane(32)] uint4 ----
    for (int i = t; i < 8192; i += 512) {
        int ws = i & 3, ln = (i >> 2) & 31;
        int np = (i >> 7) & 3, ks = (i >> 9) & 3, g = (i >> 11) & 3;
        int krow = STATE_DIM + ks * 16 + (ws & 1) * 8 + (ln & 3) * 2;
        int col  = g * 64 + np * 16 + (ws >> 1) * 8 + (ln >> 2);
        sW1f[i] = pk(W1[krow * HID + col], W1[(krow + 1) * HID + col]);
    }
    if (t < 128) { sB2[t] = b2[t]; sW3[t] = W3[t]; sOut[t] = 0.f; }

    // ---- af staging: thread t fills 2 A-frag uint4 slots per tile ----
    // slot idx in [0,1024): rg16 = idx>>7 (8), ks = (idx>>5)&3, ln = idx&31
    const int s_ln = t & 31;
    const int s_rowoff = (s_ln >> 2);
    const int s_coloff = (s_ln & 3) * 2;

    auto load_af = [&](int tl, float2* p) {
#pragma unroll
        for (int j = 0; j < 2; j++) {
            int idx = t + j * 512;
            int rg16 = idx >> 7, ks = (idx >> 5) & 3;
            const float* base = af + (size_t)(tl * TILE_M + rg16 * 16 + s_rowoff) * AFEAT
                                   + ks * 16 + s_coloff;
            p[j * 4 + 0] = *(const float2*)(base);
            p[j * 4 + 1] = *(const float2*)(base + 8 * AFEAT);
            p[j * 4 + 2] = *(const float2*)(base + 8);
            p[j * 4 + 3] = *(const float2*)(base + 8 * AFEAT + 8);
        }
    };
    auto store_af = [&](const float2* p, int buf) {
#pragma unroll
        for (int j = 0; j < 2; j++) {
            int idx = t + j * 512;
            uint4 v;
            v.x = pk(p[j * 4 + 0].x, p[j * 4 + 0].y);   // (r,   k0)
            v.y = pk(p[j * 4 + 1].x, p[j * 4 + 1].y);   // (r+8, k0)
            v.z = pk(p[j * 4 + 2].x, p[j * 4 + 2].y);   // (r,   k0+8)
            v.w = pk(p[j * 4 + 3].x, p[j * 4 + 3].y);   // (r+8, k0+8)
            sAfq[buf * 1024 + idx] = v;
        }
    };
    auto stage_hs = [&](int tl, int buf) {
        int r0 = tl * TILE_M;
        int blo = r0 / KACT;
        int bhi = (r0 + TILE_M - 1) / KACT;
        sHS[buf * 512 + t] = g_hstate[(t < 256 ? blo : bhi) * HID + (t & 255)];
    };

    // ---- prologue ----
    int tile = blockIdx.x;
    {
        float2 p[8];
        load_af(tile, p);
        store_af(p, 0);
        stage_hs(tile, 0);
    }
    __syncthreads();

    const float bias3 = __ldg(b3);
    const uint4* w1v = (const uint4*)sW1f;
    const uint4* w2v = (const uint4*)sW2f;
    const uint4* h1v = (const uint4*)sH1f;

    int it = 0;
    for (; tile < NTILES; tile += gridDim.x, it++) {
        const int row0 = tile * TILE_M;
        const int ntile = tile + gridDim.x;
        const int cur = it & 1, nxt = cur ^ 1;
        const int split = (row0 / KACT + 1) * KACT - row0;

        // ---- prefetch next tile's af (gmem latency overlaps L1 GEMM) ----
        float2 p[8];
        if (ntile < NTILES) load_af(ntile, p);

        // ---- L1: C = af @ W1a, init C = h_state (exact fp32) ----
        // C-frag: bit0 = col parity, bit1 = row+8
        float acc[2][8][4];
        const float* hsc = sHS + cur * 512;
#pragma unroll
        for (int mf = 0; mf < 2; mf++) {
            const int r = mg * 32 + mf * 16 + (lane >> 2);
#pragma unroll
            for (int nt = 0; nt < 8; nt++)
#pragma unroll
            for (int rg = 0; rg < 4; rg++) {
                int rr = r + (rg >> 1) * 8;
                int c = ng * 64 + nt * 8 + 2 * (lane & 3) + (rg & 1);
                acc[mf][nt][rg] = hsc[(rr >= split ? 256 : 0) + c];
            }
        }
#pragma unroll
        for (int ks = 0; ks < 4; ks++) {
            // A-frags from SMEM stage: rg16 = mg*2 + mf
            uint4 a0 = sAfq[cur * 1024 + ((mg * 2 + 0) * 4 + ks) * 32 + lane];
            uint4 a1 = sAfq[cur * 1024 + ((mg * 2 + 1) * 4 + ks) * 32 + lane];
#pragma unroll
            for (int np = 0; np < 4; np++) {
                uint4 b = w1v[((ng * 4 + ks) * 4 + np) * 32 + lane];
                mma16(acc[0][np * 2],     a0, b.x, b.y);
                mma16(acc[0][np * 2 + 1], a0, b.z, b.w);
                mma16(acc[1][np * 2],     a1, b.x, b.y);
                mma16(acc[1][np * 2 + 1], a1, b.z, b.w);
            }
        }
        // ---- ep1: relu -> f16 pairs -> sH1f as L2 A-frags ----
        // sH1f: [m16(8)][k16(16)][lane] uint4
#pragma unroll
        for (int mf = 0; mf < 2; mf++)
#pragma unroll
        for (int q = 0; q < 4; q++) {
            uint4 v;
            v.x = pkr(acc[mf][2 * q][0],     acc[mf][2 * q][1]);
            v.y = pkr(acc[mf][2 * q][2],     acc[mf][2 * q][3]);
            v.z = pkr(acc[mf][2 * q + 1][0], acc[mf][2 * q + 1][1]);
            v.w = pkr(acc[mf][2 * q + 1][2], acc[mf][2 * q + 1][3]);
            ((uint4*)sH1f)[((mg * 2 + mf) * 16 + ng * 4 + q) * 32 + lane] = v;
        }
        __syncthreads();   // S1: h1 ready

        // ---- stage next tile while L2 runs ----
        if (ntile < NTILES) {
            store_af(p, nxt);
            stage_hs(ntile, nxt);
        }

        // ---- L2: C2 = h1 @ W2 ----
        float acc2[2][4][4];
#pragma unroll
        for (int mf = 0; mf < 2; mf++)
#pragma unroll
        for (int nt = 0; nt < 4; nt++)
#pragma unroll
        for (int rg = 0; rg < 4; rg++) acc2[mf][nt][rg] = 0.f;
#pragma unroll
        for (int ks = 0; ks < 16; ks++) {
            uint4 a0 = h1v[((mg * 2 + 0) * 16 + ks) * 32 + lane];
            uint4 a1 = h1v[((mg * 2 + 1) * 16 + ks) * 32 + lane];
#pragma unroll
            for (int np = 0; np < 2; np++) {
                uint4 b = w2v[((ng * 16 + ks) * 2 + np) * 32 + lane];
                mma16(acc2[0][np * 2],     a0, b.x, b.y);
                mma16(acc2[0][np * 2 + 1], a0, b.z, b.w);
                mma16(acc2[1][np * 2],     a1, b.x, b.y);
                mma16(acc2[1][np * 2 + 1], a1, b.z, b.w);
            }
        }

        // ---- L3: out = relu(C2 + b2) . W3 + b3 ----
#pragma unroll
        for (int mf = 0; mf < 2; mf++) {
            float part[2] = {0.f, 0.f};
#pragma unroll
            for (int nt = 0; nt < 4; nt++)
#pragma unroll
            for (int rg = 0; rg < 4; rg++) {
                int c = ng * 32 + nt * 8 + 2 * (lane & 3) + (rg & 1);
                float v = fmaxf(acc2[mf][nt][rg] + sB2[c], 0.f);
                part[rg >> 1] += v * sW3[c];
            }
#pragma unroll
            for (int rb = 0; rb < 2; rb++) {
                float v = part[rb];
                v += __shfl_xor_sync(0xffffffffu, v, 1);
                v += __shfl_xor_sync(0xffffffffu, v, 2);
                if ((lane & 3) == 0)
                    atomicAdd(&sOut[mg * 32 + mf * 16 + rb * 8 + (lane >> 2)], v);
            }
        }
        __syncthreads();   // S2: L3 atomics done, h1 reads done
        if (t < 128) {
            out[row0 + t] = sOut[t] + bias3;
            sOut[t] = 0.f;
        }
        __syncthreads();   // S3: buffers free
    }
}

// ---------------------------------------------------------------------------
extern "C" void kernel_launch(void* const* d_in, const int* in_sizes, int n_in,
                              void* d_out, int out_size)
{
    const float* state = (const float*)d_in[0];
    const float* afeats = (const float*)d_in[1];
    const float* W1    = (const float*)d_in[2];
    const float* b1    = (const float*)d_in[3];
    const float* W2    = (const float*)d_in[4];
    const float* b2    = (const float*)d_in[5];
    const float* W3    = (const float*)d_in[6];
    const float* b3    = (const float*)d_in[7];
    float* out = (float*)d_out;
    (void)in_sizes; (void)n_in; (void)out_size;

    static int sm_count = 0;
    if (sm_count == 0) {
        cudaDeviceGetAttribute(&sm_count, cudaDevAttrMultiProcessorCount, 0);
        if (sm_count <= 0) sm_count = 148;
        cudaFuncSetAttribute(actor_main,
                             cudaFuncAttributeMaxDynamicSharedMemorySize, SMEM_BYTES);
    }

    hstate_kernel<<<64, 256>>>(state, W1, b1);
    actor_main<<<sm_count, 512, SMEM_BYTES>>>(afeats, W1, W2, b2, W3, b3, out);
}

// round 11
// speedup vs baseline: 1.4156x; 1.1313x over previous
#include <cuda_runtime.h>
#include <cuda_fp16.h>
#include <cstdint>

#define STATE_DIM 512
#define AFEAT 64
#define HID 256
#define HID2 128
#define KACT 1000
#define NROWS 256000
#define TILE_M 128
#define NTILES 2000            // 256000 / 128

__device__ float g_hstate[256 * HID];

__device__ __forceinline__ uint32_t pk(float lo, float hi) {
    __half2 h = __floats2half2_rn(lo, hi);      // low 16 bits = lo
    return *(uint32_t*)&h;
}
__device__ __forceinline__ uint32_t pkr(float lo, float hi) {
    return pk(fmaxf(lo, 0.f), fmaxf(hi, 0.f));
}

// m16n8k16 f16 MMA, f32 accum, C += A*B (row.col)
__device__ __forceinline__ void mma16(float* c, const uint4& a, uint32_t b0, uint32_t b1) {
    asm volatile("mma.sync.aligned.m16n8k16.row.col.f32.f16.f16.f32 "
        "{%0,%1,%2,%3}, {%4,%5,%6,%7}, {%8,%9}, {%0,%1,%2,%3};"
        : "+f"(c[0]), "+f"(c[1]), "+f"(c[2]), "+f"(c[3])
        : "r"(a.x), "r"(a.y), "r"(a.z), "r"(a.w), "r"(b0), "r"(b1));
}

// ---------------------------------------------------------------------------
// hstate: h_state[b][j] = state[b] . W1[:512,j] + b1[j]   (exact fp32)
// One block per batch row -> 256 blocks, full-chip spread.
// ---------------------------------------------------------------------------
__global__ __launch_bounds__(256) void hstate_kernel(
    const float* __restrict__ state,
    const float* __restrict__ W1,
    const float* __restrict__ b1)
{
    __shared__ float s[STATE_DIM];
    const int b = blockIdx.x;
    const int t = threadIdx.x;
    s[t]       = state[b * STATE_DIM + t];
    s[t + 256] = state[b * STATE_DIM + 256 + t];
    __syncthreads();

    float a = b1[t];
#pragma unroll 8
    for (int k = 0; k < STATE_DIM; k++)
        a = fmaf(s[k], W1[k * HID + t], a);
    g_hstate[b * HID + t] = a;
}

// ---------------------------------------------------------------------------
// Main fused MLP. 512 threads = 16 warps, 4(M)x4(N) grid, TILE_M=128.
// Each warp: 32 rows (2 m16 frags). A1 staged in double-buffered SMEM frags.
// 2 barriers/tile; L3 partials via ng-slotted plain stores (double-buffered),
// reduced + written to gmem at the NEXT iteration top.
//
// B-frag uint4: x=(n8=0,k0..7) y=(n8=0,k8..15) z=(n8=1,k0..7) w=(n8=1,k8..15)
// A-frag uint4: x=(r,k0..) y=(r+8,k0..) z=(r,k8..) w=(r+8,k8..), f16x2 lo=even k
//
// SMEM (float units):
//  sW2f 16384 | sW1f 8192 | sH1f 16384 | sAf 2x4096 | sHS 2x512 | sB2/sW3 256 | sOutP 2x512
// ---------------------------------------------------------------------------
#define OFF_W2F 0
#define OFF_W1F 16384
#define OFF_H1F 24576
#define OFF_AF  40960
#define OFF_HS  49152
#define OFF_B2  50176
#define OFF_W3  50304
#define OFF_OUT 50432
#define SMEM_FLOATS 51456
#define SMEM_BYTES (SMEM_FLOATS * 4)

__global__ void __launch_bounds__(512, 1) actor_main(
    const float* __restrict__ af, const float* __restrict__ W1,
    const float* __restrict__ W2, const float* __restrict__ b2,
    const float* __restrict__ W3, const float* __restrict__ b3,
    float* __restrict__ out)
{
    extern __shared__ float sm[];
    uint32_t* sW2f = (uint32_t*)(sm + OFF_W2F);
    uint32_t* sW1f = (uint32_t*)(sm + OFF_W1F);
    uint32_t* sH1f = (uint32_t*)(sm + OFF_H1F);
    uint4*    sAfq = (uint4*)(sm + OFF_AF);      // [2][1024] uint4
    float* sHS  = sm + OFF_HS;     // [2][512]
    float* sB2  = sm + OFF_B2;
    float* sW3  = sm + OFF_W3;
    float* sOutP = sm + OFF_OUT;   // [2][128 rows][4 ng slots]

    const int t = threadIdx.x;
    const int lane = t & 31;
    const int w = t >> 5;
    const int mg = w & 3;          // rows mg*32 .. +31
    const int ng = w >> 2;         // L1: cols ng*64..; L2: cols ng*32..

    // ---- build W2 frags: [ng(4)][ks(16)][np(2)][lane(32)] uint4 ----
    for (int i = t; i < 16384; i += 512) {
        int ws = i & 3, ln = (i >> 2) & 31;
        int np = (i >> 7) & 1, ks = (i >> 8) & 15, g = (i >> 12) & 3;
        int krow = ks * 16 + (ws & 1) * 8 + (ln & 3) * 2;
        int col  = g * 32 + np * 16 + (ws >> 1) * 8 + (ln >> 2);
        sW2f[i] = pk(W2[krow * HID2 + col], W2[(krow + 1) * HID2 + col]);
    }
    // ---- build W1a frags: [ng(4)][ks(4)][np(4)][lane(32)] uint4 ----
    for (int i = t; i < 8192; i += 512) {
        int ws = i & 3, ln = (i >> 2) & 31;
        int np = (i >> 7) & 3, ks = (i >> 9) & 3, g = (i >> 11) & 3;
        int krow = STATE_DIM + ks * 16 + (ws & 1) * 8 + (ln & 3) * 2;
        int col  = g * 64 + np * 16 + (ws >> 1) * 8 + (ln >> 2);
        sW1f[i] = pk(W1[krow * HID + col], W1[(krow + 1) * HID + col]);
    }
    if (t < 128) { sB2[t] = b2[t]; sW3[t] = W3[t]; }

    // ---- af staging: thread t fills 2 A-frag uint4 slots per tile ----
    const int s_ln = t & 31;
    const int s_rowoff = (s_ln >> 2);
    const int s_coloff = (s_ln & 3) * 2;

    // load + pack immediately: 8 uint32 live instead of 16 floats
    auto load_af = [&](int tl, uint32_t* pp) {
#pragma unroll
        for (int j = 0; j < 2; j++) {
            int idx = t + j * 512;
            int rg16 = idx >> 7, ks = (idx >> 5) & 3;
            const float* base = af + (size_t)(tl * TILE_M + rg16 * 16 + s_rowoff) * AFEAT
                                   + ks * 16 + s_coloff;
            float2 v0 = *(const float2*)(base);
            float2 v1 = *(const float2*)(base + 8 * AFEAT);
            float2 v2 = *(const float2*)(base + 8);
            float2 v3 = *(const float2*)(base + 8 * AFEAT + 8);
            pp[j * 4 + 0] = pk(v0.x, v0.y);   // (r,   k0)
            pp[j * 4 + 1] = pk(v1.x, v1.y);   // (r+8, k0)
            pp[j * 4 + 2] = pk(v2.x, v2.y);   // (r,   k0+8)
            pp[j * 4 + 3] = pk(v3.x, v3.y);   // (r+8, k0+8)
        }
    };
    auto store_af = [&](const uint32_t* pp, int buf) {
#pragma unroll
        for (int j = 0; j < 2; j++) {
            uint4 v = make_uint4(pp[j * 4 + 0], pp[j * 4 + 1],
                                 pp[j * 4 + 2], pp[j * 4 + 3]);
            sAfq[buf * 1024 + t + j * 512] = v;
        }
    };
    auto stage_hs = [&](int tl, int buf) {
        int r0 = tl * TILE_M;
        int blo = r0 / KACT;
        int bhi = (r0 + TILE_M - 1) / KACT;
        sHS[buf * 512 + t] = g_hstate[(t < 256 ? blo : bhi) * HID + (t & 255)];
    };

    // ---- prologue ----
    int tile = blockIdx.x;
    {
        uint32_t pp[8];
        load_af(tile, pp);
        store_af(pp, 0);
        stage_hs(tile, 0);
    }
    __syncthreads();

    const float bias3 = __ldg(b3);
    const uint4* w1v = (const uint4*)sW1f;
    const uint4* w2v = (const uint4*)sW2f;
    const uint4* h1v = (const uint4*)sH1f;
    const int G = gridDim.x;

    int it = 0;
    for (; tile < NTILES; tile += G, it++) {
        const int row0 = tile * TILE_M;
        const int ntile = tile + G;
        const int cur = it & 1, nxt = cur ^ 1;
        const int split = (row0 / KACT + 1) * KACT - row0;

        // ---- write out(tile-G): reduce ng-slots from sOutP[nxt] ----
        if (it >= 1 && t < 128) {
            float4 v = *(float4*)(sOutP + nxt * 512 + t * 4);
            out[(row0 - G * TILE_M) + t] = v.x + v.y + v.z + v.w + bias3;
        }

        // ---- prefetch next tile's af (gmem latency overlaps L1 GEMM) ----
        uint32_t pp[8];
        if (ntile < NTILES) load_af(ntile, pp);

        // ---- L1: C = af @ W1a, init C = h_state (exact fp32) ----
        // C-frag: bit0 = col parity, bit1 = row+8
        float acc[2][8][4];
        const float* hsc = sHS + cur * 512;
#pragma unroll
        for (int mf = 0; mf < 2; mf++) {
            const int r = mg * 32 + mf * 16 + (lane >> 2);
#pragma unroll
            for (int nt = 0; nt < 8; nt++)
#pragma unroll
            for (int rg = 0; rg < 4; rg++) {
                int rr = r + (rg >> 1) * 8;
                int c = ng * 64 + nt * 8 + 2 * (lane & 3) + (rg & 1);
                acc[mf][nt][rg] = hsc[(rr >= split ? 256 : 0) + c];
            }
        }
#pragma unroll
        for (int ks = 0; ks < 4; ks++) {
            uint4 a0 = sAfq[cur * 1024 + ((mg * 2 + 0) * 4 + ks) * 32 + lane];
            uint4 a1 = sAfq[cur * 1024 + ((mg * 2 + 1) * 4 + ks) * 32 + lane];
#pragma unroll
            for (int np = 0; np < 4; np++) {
                uint4 b = w1v[((ng * 4 + ks) * 4 + np) * 32 + lane];
                mma16(acc[0][np * 2],     a0, b.x, b.y);
                mma16(acc[0][np * 2 + 1], a0, b.z, b.w);
                mma16(acc[1][np * 2],     a1, b.x, b.y);
                mma16(acc[1][np * 2 + 1], a1, b.z, b.w);
            }
        }
        // ---- ep1: relu -> f16 pairs -> sH1f as L2 A-frags ----
        // sH1f: [m16(8)][k16(16)][lane] uint4
#pragma unroll
        for (int mf = 0; mf < 2; mf++)
#pragma unroll
        for (int q = 0; q < 4; q++) {
            uint4 v;
            v.x = pkr(acc[mf][2 * q][0],     acc[mf][2 * q][1]);
            v.y = pkr(acc[mf][2 * q][2],     acc[mf][2 * q][3]);
            v.z = pkr(acc[mf][2 * q + 1][0], acc[mf][2 * q + 1][1]);
            v.w = pkr(acc[mf][2 * q + 1][2], acc[mf][2 * q + 1][3]);
            ((uint4*)sH1f)[((mg * 2 + mf) * 16 + ng * 4 + q) * 32 + lane] = v;
        }
        __syncthreads();   // S1: h1 ready, prev-buffer reads all done

        // ---- stage next tile while L2 runs ----
        if (ntile < NTILES) {
            store_af(pp, nxt);
            stage_hs(ntile, nxt);
        }

        // ---- L2: C2 = h1 @ W2 ----
        float acc2[2][4][4];
#pragma unroll
        for (int mf = 0; mf < 2; mf++)
#pragma unroll
        for (int nt = 0; nt < 4; nt++)
#pragma unroll
        for (int rg = 0; rg < 4; rg++) acc2[mf][nt][rg] = 0.f;
#pragma unroll
        for (int ks = 0; ks < 16; ks++) {
            uint4 a0 = h1v[((mg * 2 + 0) * 16 + ks) * 32 + lane];
            uint4 a1 = h1v[((mg * 2 + 1) * 16 + ks) * 32 + lane];
#pragma unroll
            for (int np = 0; np < 2; np++) {
                uint4 b = w2v[((ng * 16 + ks) * 2 + np) * 32 + lane];
                mma16(acc2[0][np * 2],     a0, b.x, b.y);
                mma16(acc2[0][np * 2 + 1], a0, b.z, b.w);
                mma16(acc2[1][np * 2],     a1, b.x, b.y);
                mma16(acc2[1][np * 2 + 1], a1, b.z, b.w);
            }
        }

        // ---- L3: relu(C2 + b2) . W3 partials -> sOutP[cur][row][ng] ----
#pragma unroll
        for (int mf = 0; mf < 2; mf++) {
            float part[2] = {0.f, 0.f};
#pragma unroll
            for (int nt = 0; nt < 4; nt++)
#pragma unroll
            for (int rg = 0; rg < 4; rg++) {
                int c = ng * 32 + nt * 8 + 2 * (lane & 3) + (rg & 1);
                float v = fmaxf(acc2[mf][nt][rg] + sB2[c], 0.f);
                part[rg >> 1] += v * sW3[c];
            }
#pragma unroll
            for (int rb = 0; rb < 2; rb++) {
                float v = part[rb];
                v += __shfl_xor_sync(0xffffffffu, v, 1);
                v += __shfl_xor_sync(0xffffffffu, v, 2);
                if ((lane & 3) == 0)
                    sOutP[cur * 512 + (mg * 32 + mf * 16 + rb * 8 + (lane >> 2)) * 4 + ng] = v;
            }
        }
        __syncthreads();   // S2: L3 stores + h1 reads done; buffers flip
    }

    // ---- drain: write the final tile's output ----
    if (it >= 1 && t < 128) {
        const int last = tile - G;           // last processed tile
        float4 v = *(float4*)(sOutP + ((it - 1) & 1) * 512 + t * 4);
        out[last * TILE_M + t] = v.x + v.y + v.z + v.w + bias3;
    }
}

// ---------------------------------------------------------------------------
extern "C" void kernel_launch(void* const* d_in, const int* in_sizes, int n_in,
                              void* d_out, int out_size)
{
    const float* state = (const float*)d_in[0];
    const float* afeats = (const float*)d_in[1];
    const float* W1    = (const float*)d_in[2];
    const float* b1    = (const float*)d_in[3];
    const float* W2    = (const float*)d_in[4];
    const float* b2    = (const float*)d_in[5];
    const float* W3    = (const float*)d_in[6];
    const float* b3    = (const float*)d_in[7];
    float* out = (float*)d_out;
    (void)in_sizes; (void)n_in; (void)out_size;

    static int sm_count = 0;
    if (sm_count == 0) {
        cudaDeviceGetAttribute(&sm_count, cudaDevAttrMultiProcessorCount, 0);
        if (sm_count <= 0) sm_count = 148;
        cudaFuncSetAttribute(actor_main,
                             cudaFuncAttributeMaxDynamicSharedMemorySize, SMEM_BYTES);
    }

    hstate_kernel<<<256, 256>>>(state, W1, b1);
    actor_main<<<sm_count, 512, SMEM_BYTES>>>(afeats, W1, W2, b2, W3, b3, out);
}

// round 12
// speedup vs baseline: 1.4241x; 1.0060x over previous
#include <cuda_runtime.h>
#include <cuda_fp16.h>
#include <cstdint>

#define STATE_DIM 512
#define AFEAT 64
#define HID 256
#define HID2 128
#define KACT 1000
#define NROWS 256000
#define TILE_M 64
#define NTILES 4000            // 256000 / 64

__device__ float g_hstate[256 * HID];

__device__ __forceinline__ uint32_t pk(float lo, float hi) {
    __half2 h = __floats2half2_rn(lo, hi);      // low 16 bits = lo
    return *(uint32_t*)&h;
}
__device__ __forceinline__ uint32_t pkr(float lo, float hi) {
    return pk(fmaxf(lo, 0.f), fmaxf(hi, 0.f));
}

// m16n8k16 f16 MMA, f32 accum, C += A*B (row.col)
__device__ __forceinline__ void mma16(float* c, const uint4& a, uint32_t b0, uint32_t b1) {
    asm volatile("mma.sync.aligned.m16n8k16.row.col.f32.f16.f16.f32 "
        "{%0,%1,%2,%3}, {%4,%5,%6,%7}, {%8,%9}, {%0,%1,%2,%3};"
        : "+f"(c[0]), "+f"(c[1]), "+f"(c[2]), "+f"(c[3])
        : "r"(a.x), "r"(a.y), "r"(a.z), "r"(a.w), "r"(b0), "r"(b1));
}

#define GBAR(gid) asm volatile("bar.sync %0, 256;" :: "r"((gid) + 1) : "memory")

// ---------------------------------------------------------------------------
// hstate: tiled 16 rows x 64 cols per block -> W1 reads amortized x16.
// Accumulation order (k = 0..511 sequential) identical to prior rounds.
// ---------------------------------------------------------------------------
__global__ __launch_bounds__(256) void hstate_kernel(
    const float* __restrict__ state,
    const float* __restrict__ W1,
    const float* __restrict__ b1)
{
    __shared__ float s[16 * STATE_DIM];        // 32 KB
    const int bg = blockIdx.x >> 2;            // 16-row batch group
    const int cg = blockIdx.x & 3;             // 64-col group
    const int t = threadIdx.x;

    for (int i = t * 4; i < 16 * STATE_DIM; i += 1024)
        *(float4*)&s[i] = *(const float4*)&state[bg * 16 * STATE_DIM + i];
    __syncthreads();

    const int c = t & 63;
    const int rq = t >> 6;                     // rows rq*4 .. +3
    const int col = cg * 64 + c;
    float a0, a1, a2, a3;
    a0 = a1 = a2 = a3 = b1[col];
    const float* s0 = s + (rq * 4) * STATE_DIM;
#pragma unroll 8
    for (int k = 0; k < STATE_DIM; k++) {
        float wv = W1[k * HID + col];
        a0 = fmaf(s0[k], wv, a0);
        a1 = fmaf(s0[512 + k], wv, a1);
        a2 = fmaf(s0[1024 + k], wv, a2);
        a3 = fmaf(s0[1536 + k], wv, a3);
    }
    const int r = bg * 16 + rq * 4;
    g_hstate[(r + 0) * HID + col] = a0;
    g_hstate[(r + 1) * HID + col] = a1;
    g_hstate[(r + 2) * HID + col] = a2;
    g_hstate[(r + 3) * HID + col] = a3;
}

// ---------------------------------------------------------------------------
// Main fused MLP. 512 threads = 2 groups x 8 warps. Each group independently
// pipelines tiles of 64 rows (warp grid 2M x 4N, m=32/warp) with its own
// named barrier -> groups drift into different phases, overlapping MMA-dense
// and LDS-dense stretches on each SMSP.
//
// SMEM (float units):
//  sW2f 16384 | sW1f 8192 | sB2 128 | sW3 128 |
//  per group (13824): sAf 2x2048 | sH1f 8192 | sHS 2x512 | sOutP 2x256
// ---------------------------------------------------------------------------
#define OFF_W2F 0
#define OFF_W1F 16384
#define OFF_B2  24576
#define OFF_W3  24704
#define OFF_G0  24832
#define GSTRIDE 13824
#define GOFF_AF  0
#define GOFF_H1F 4096
#define GOFF_HS  12288
#define GOFF_OUT 13312
#define SMEM_FLOATS (24832 + 2 * 13824)
#define SMEM_BYTES (SMEM_FLOATS * 4)

__global__ void __launch_bounds__(512, 1) actor_main(
    const float* __restrict__ af, const float* __restrict__ W1,
    const float* __restrict__ W2, const float* __restrict__ b2,
    const float* __restrict__ W3, const float* __restrict__ b3,
    float* __restrict__ out)
{
    extern __shared__ float sm[];
    uint32_t* sW2f = (uint32_t*)(sm + OFF_W2F);
    uint32_t* sW1f = (uint32_t*)(sm + OFF_W1F);
    float* sB2  = sm + OFF_B2;
    float* sW3  = sm + OFF_W3;

    const int t = threadIdx.x;
    const int lane = t & 31;
    const int w = t >> 5;
    const int g = w >> 3;          // group 0/1
    const int wg = w & 7;          // warp in group
    const int mg = wg & 1;         // rows mg*32 .. +31
    const int ng = wg >> 1;        // L1: cols ng*64..; L2: cols ng*32..
    const int tg = t & 255;        // thread in group

    float* GB = sm + OFF_G0 + g * GSTRIDE;
    uint4*    sAfq  = (uint4*)(GB + GOFF_AF);     // [2][512] uint4
    uint32_t* sH1f  = (uint32_t*)(GB + GOFF_H1F); // 2048 uint4
    float*    sHS   = GB + GOFF_HS;               // [2][512]
    float*    sOutP = GB + GOFF_OUT;              // [2][64*4]

    // ---- build W2 frags: [ng(4)][ks(16)][np(2)][lane(32)] uint4 ----
    for (int i = t; i < 16384; i += 512) {
        int ws = i & 3, ln = (i >> 2) & 31;
        int np = (i >> 7) & 1, ks = (i >> 8) & 15, gg = (i >> 12) & 3;
        int krow = ks * 16 + (ws & 1) * 8 + (ln & 3) * 2;
        int col  = gg * 32 + np * 16 + (ws >> 1) * 8 + (ln >> 2);
        sW2f[i] = pk(W2[krow * HID2 + col], W2[(krow + 1) * HID2 + col]);
    }
    // ---- build W1a frags: [ng(4)][ks(4)][np(4)][lane(32)] uint4 ----
    for (int i = t; i < 8192; i += 512) {
        int ws = i & 3, ln = (i >> 2) & 31;
        int np = (i >> 7) & 3, ks = (i >> 9) & 3, gg = (i >> 11) & 3;
        int krow = STATE_DIM + ks * 16 + (ws & 1) * 8 + (ln & 3) * 2;
        int col  = gg * 64 + np * 16 + (ws >> 1) * 8 + (ln >> 2);
        sW1f[i] = pk(W1[krow * HID + col], W1[(krow + 1) * HID + col]);
    }
    if (t < 128) { sB2[t] = b2[t]; sW3[t] = W3[t]; }

    // ---- af staging: each group thread fills 2 A-frag uint4 per tile ----
    const int s_rowoff = (lane >> 2);
    const int s_coloff = (lane & 3) * 2;

    auto load_af = [&](int tl, uint32_t* pp) {
#pragma unroll
        for (int j = 0; j < 2; j++) {
            int idx = tg + j * 256;              // 0..511
            int rg16 = idx >> 7, ks = (idx >> 5) & 3;
            const float* base = af + (size_t)(tl * TILE_M + rg16 * 16 + s_rowoff) * AFEAT
                                   + ks * 16 + s_coloff;
            float2 v0 = *(const float2*)(base);
            float2 v1 = *(const float2*)(base + 8 * AFEAT);
            float2 v2 = *(const float2*)(base + 8);
            float2 v3 = *(const float2*)(base + 8 * AFEAT + 8);
            pp[j * 4 + 0] = pk(v0.x, v0.y);   // (r,   k0)
            pp[j * 4 + 1] = pk(v1.x, v1.y);   // (r+8, k0)
            pp[j * 4 + 2] = pk(v2.x, v2.y);   // (r,   k0+8)
            pp[j * 4 + 3] = pk(v3.x, v3.y);   // (r+8, k0+8)
        }
    };
    auto store_af = [&](const uint32_t* pp, int buf) {
#pragma unroll
        for (int j = 0; j < 2; j++)
            sAfq[buf * 512 + tg + j * 256] =
                make_uint4(pp[j * 4 + 0], pp[j * 4 + 1], pp[j * 4 + 2], pp[j * 4 + 3]);
    };
    auto stage_hs = [&](int tl, int buf) {
        int r0 = tl * TILE_M;
        int blo = r0 / KACT;
        int bhi = (r0 + TILE_M - 1) / KACT;
        sHS[buf * 512 + tg]       = g_hstate[blo * HID + tg];
        sHS[buf * 512 + 256 + tg] = g_hstate[bhi * HID + tg];
    };

    __syncthreads();               // weights ready (both groups)

    const int G = gridDim.x;
    const int tstep = 2 * G;
    int tile = blockIdx.x * 2 + g;

    // ---- prologue: stage first tile for this group ----
    {
        uint32_t pp[8];
        load_af(tile, pp);
        store_af(pp, 0);
        stage_hs(tile, 0);
    }
    GBAR(g);

    const float bias3 = __ldg(b3);
    const uint4* w1v = (const uint4*)sW1f;
    const uint4* w2v = (const uint4*)sW2f;
    const uint4* h1v = (const uint4*)sH1f;

    int it = 0;
    for (; tile < NTILES; tile += tstep, it++) {
        const int row0 = tile * TILE_M;
        const int ntile = tile + tstep;
        const int cur = it & 1, nxt = cur ^ 1;
        const int split = (row0 / KACT + 1) * KACT - row0;

        // ---- write out(tile - tstep): reduce ng-slots from sOutP[nxt] ----
        if (it >= 1 && tg < 64) {
            float4 v = *(float4*)(sOutP + nxt * 256 + tg * 4);
            out[row0 - tstep * TILE_M + tg] = v.x + v.y + v.z + v.w + bias3;
        }

        // ---- prefetch next tile's af ----
        uint32_t pp[8];
        if (ntile < NTILES) load_af(ntile, pp);

        // ---- L1: C = af @ W1a, init C = h_state (exact fp32) ----
        // C-frag: bit0 = col parity, bit1 = row+8
        float acc[2][8][4];
        const float* hsc = sHS + cur * 512;
#pragma unroll
        for (int mf = 0; mf < 2; mf++) {
            const int r = mg * 32 + mf * 16 + (lane >> 2);
#pragma unroll
            for (int nt = 0; nt < 8; nt++)
#pragma unroll
            for (int rg = 0; rg < 4; rg++) {
                int rr = r + (rg >> 1) * 8;
                int c = ng * 64 + nt * 8 + 2 * (lane & 3) + (rg & 1);
                acc[mf][nt][rg] = hsc[(rr >= split ? 256 : 0) + c];
            }
        }
#pragma unroll
        for (int ks = 0; ks < 4; ks++) {
            uint4 a0 = sAfq[cur * 512 + ((mg * 2 + 0) * 4 + ks) * 32 + lane];
            uint4 a1 = sAfq[cur * 512 + ((mg * 2 + 1) * 4 + ks) * 32 + lane];
#pragma unroll
            for (int np = 0; np < 4; np++) {
                uint4 b = w1v[((ng * 4 + ks) * 4 + np) * 32 + lane];
                mma16(acc[0][np * 2],     a0, b.x, b.y);
                mma16(acc[0][np * 2 + 1], a0, b.z, b.w);
                mma16(acc[1][np * 2],     a1, b.x, b.y);
                mma16(acc[1][np * 2 + 1], a1, b.z, b.w);
            }
        }
        // ---- ep1: relu -> f16 pairs -> sH1f as L2 A-frags ----
        // sH1f: [m16(4)][k16(16)][lane] uint4
#pragma unroll
        for (int mf = 0; mf < 2; mf++)
#pragma unroll
        for (int q = 0; q < 4; q++) {
            uint4 v;
            v.x = pkr(acc[mf][2 * q][0],     acc[mf][2 * q][1]);
            v.y = pkr(acc[mf][2 * q][2],     acc[mf][2 * q][3]);
            v.z = pkr(acc[mf][2 * q + 1][0], acc[mf][2 * q + 1][1]);
            v.w = pkr(acc[mf][2 * q + 1][2], acc[mf][2 * q + 1][3]);
            ((uint4*)sH1f)[((mg * 2 + mf) * 16 + ng * 4 + q) * 32 + lane] = v;
        }
        GBAR(g);   // S1: h1 ready, prev-buffer reads all done

        // ---- stage next tile while L2 runs ----
        if (ntile < NTILES) {
            store_af(pp, nxt);
            stage_hs(ntile, nxt);
        }

        // ---- L2: C2 = h1 @ W2 ----
        float acc2[2][4][4];
#pragma unroll
        for (int mf = 0; mf < 2; mf++)
#pragma unroll
        for (int nt = 0; nt < 4; nt++)
#pragma unroll
        for (int rg = 0; rg < 4; rg++) acc2[mf][nt][rg] = 0.f;
#pragma unroll
        for (int ks = 0; ks < 16; ks++) {
            uint4 a0 = h1v[((mg * 2 + 0) * 16 + ks) * 32 + lane];
            uint4 a1 = h1v[((mg * 2 + 1) * 16 + ks) * 32 + lane];
#pragma unroll
            for (int np = 0; np < 2; np++) {
                uint4 b = w2v[((ng * 16 + ks) * 2 + np) * 32 + lane];
                mma16(acc2[0][np * 2],     a0, b.x, b.y);
                mma16(acc2[0][np * 2 + 1], a0, b.z, b.w);
                mma16(acc2[1][np * 2],     a1, b.x, b.y);
                mma16(acc2[1][np * 2 + 1], a1, b.z, b.w);
            }
        }

        // ---- L3: relu(C2 + b2) . W3 partials -> sOutP[cur][row][ng] ----
#pragma unroll
        for (int mf = 0; mf < 2; mf++) {
            float part[2] = {0.f, 0.f};
#pragma unroll
            for (int nt = 0; nt < 4; nt++)
#pragma unroll
            for (int rg = 0; rg < 4; rg++) {
                int c = ng * 32 + nt * 8 + 2 * (lane & 3) + (rg & 1);
                float v = fmaxf(acc2[mf][nt][rg] + sB2[c], 0.f);
                part[rg >> 1] += v * sW3[c];
            }
#pragma unroll
            for (int rb = 0; rb < 2; rb++) {
                float v = part[rb];
                v += __shfl_xor_sync(0xffffffffu, v, 1);
                v += __shfl_xor_sync(0xffffffffu, v, 2);
                if ((lane & 3) == 0)
                    sOutP[cur * 256 + (mg * 32 + mf * 16 + rb * 8 + (lane >> 2)) * 4 + ng] = v;
            }
        }
        GBAR(g);   // S2: L3 stores + h1 reads done; buffers flip
    }

    // ---- drain: write the final tile's output ----
    if (it >= 1 && tg < 64) {
        const int last = tile - tstep;
        float4 v = *(float4*)(sOutP + ((it - 1) & 1) * 256 + tg * 4);
        out[last * TILE_M + tg] = v.x + v.y + v.z + v.w + bias3;
    }
}

// ---------------------------------------------------------------------------
extern "C" void kernel_launch(void* const* d_in, const int* in_sizes, int n_in,
                              void* d_out, int out_size)
{
    const float* state = (const float*)d_in[0];
    const float* afeats = (const float*)d_in[1];
    const float* W1    = (const float*)d_in[2];
    const float* b1    = (const float*)d_in[3];
    const float* W2    = (const float*)d_in[4];
    const float* b2    = (const float*)d_in[5];
    const float* W3    = (const float*)d_in[6];
    const float* b3    = (const float*)d_in[7];
    float* out = (float*)d_out;
    (void)in_sizes; (void)n_in; (void)out_size;

    static int sm_count = 0;
    if (sm_count == 0) {
        cudaDeviceGetAttribute(&sm_count, cudaDevAttrMultiProcessorCount, 0);
        if (sm_count <= 0) sm_count = 148;
        cudaFuncSetAttribute(actor_main,
                             cudaFuncAttributeMaxDynamicSharedMemorySize, SMEM_BYTES);
    }

    hstate_kernel<<<64, 256>>>(state, W1, b1);
    actor_main<<<sm_count, 512, SMEM_BYTES>>>(afeats, W1, W2, b2, W3, b3, out);
}

// round 13
// speedup vs baseline: 1.4489x; 1.0174x over previous
#include <cuda_runtime.h>
#include <cuda_fp16.h>
#include <cstdint>

#define STATE_DIM 512
#define AFEAT 64
#define HID 256
#define HID2 128
#define KACT 1000
#define NROWS 256000
#define TILE_M 64
#define NTILES 4000            // 256000 / 64

__device__ float g_hstate[256 * HID];

__device__ __forceinline__ uint32_t pk(float lo, float hi) {
    __half2 h = __floats2half2_rn(lo, hi);      // low 16 bits = lo
    return *(uint32_t*)&h;
}
__device__ __forceinline__ uint32_t pkr(float lo, float hi) {
    return pk(fmaxf(lo, 0.f), fmaxf(hi, 0.f));
}

// m16n8k16 f16 MMA, f32 accum, C += A*B (row.col)
__device__ __forceinline__ void mma16(float* c, const uint4& a, uint32_t b0, uint32_t b1) {
    asm volatile("mma.sync.aligned.m16n8k16.row.col.f32.f16.f16.f32 "
        "{%0,%1,%2,%3}, {%4,%5,%6,%7}, {%8,%9}, {%0,%1,%2,%3};"
        : "+f"(c[0]), "+f"(c[1]), "+f"(c[2]), "+f"(c[3])
        : "r"(a.x), "r"(a.y), "r"(a.z), "r"(a.w), "r"(b0), "r"(b1));
}

#define GBAR(gid) asm volatile("bar.sync %0, 256;" :: "r"((gid) + 1) : "memory")

// ---------------------------------------------------------------------------
// hstate: 128 blocks = 64 row-groups (4 rows) x 2 col-groups (128 cols).
// 2 accumulators/thread, k ascending (bit-identical accumulation order).
// ---------------------------------------------------------------------------
__global__ __launch_bounds__(256) void hstate_kernel(
    const float* __restrict__ state,
    const float* __restrict__ W1,
    const float* __restrict__ b1)
{
    __shared__ float s[4 * STATE_DIM];         // 8 KB
    const int bg = blockIdx.x >> 1;            // 4-row batch group
    const int cg = blockIdx.x & 1;             // 128-col group
    const int t = threadIdx.x;

    for (int i = t * 4; i < 4 * STATE_DIM; i += 1024)
        *(float4*)&s[i] = *(const float4*)&state[bg * 4 * STATE_DIM + i];
    __syncthreads();

    const int col = cg * 128 + (t & 127);
    const int rh = t >> 7;                     // rows rh*2, rh*2+1
    float a0 = b1[col], a1 = a0;
    const float* s0 = s + (rh * 2) * STATE_DIM;
#pragma unroll 8
    for (int k = 0; k < STATE_DIM; k++) {
        float wv = W1[k * HID + col];
        a0 = fmaf(s0[k], wv, a0);
        a1 = fmaf(s0[STATE_DIM + k], wv, a1);
    }
    const int r = bg * 4 + rh * 2;
    g_hstate[r * HID + col]       = a0;
    g_hstate[(r + 1) * HID + col] = a1;
}

// ---------------------------------------------------------------------------
// Main fused MLP. 512 threads = 2 groups x 8 warps, per-group tile streams,
// named barriers. h_state acc-init vectorized (float2, hoisted selects).
//
// SMEM (float units):
//  sW2f 16384 | sW1f 8192 | sB2 128 | sW3 128 |
//  per group (13824): sAf 2x2048 | sH1f 8192 | sHS 2x512 | sOutP 2x256
// ---------------------------------------------------------------------------
#define OFF_W2F 0
#define OFF_W1F 16384
#define OFF_B2  24576
#define OFF_W3  24704
#define OFF_G0  24832
#define GSTRIDE 13824
#define GOFF_AF  0
#define GOFF_H1F 4096
#define GOFF_HS  12288
#define GOFF_OUT 13312
#define SMEM_FLOATS (24832 + 2 * 13824)
#define SMEM_BYTES (SMEM_FLOATS * 4)

__global__ void __launch_bounds__(512, 1) actor_main(
    const float* __restrict__ af, const float* __restrict__ W1,
    const float* __restrict__ W2, const float* __restrict__ b2,
    const float* __restrict__ W3, const float* __restrict__ b3,
    float* __restrict__ out)
{
    extern __shared__ float sm[];
    uint32_t* sW2f = (uint32_t*)(sm + OFF_W2F);
    uint32_t* sW1f = (uint32_t*)(sm + OFF_W1F);
    float* sB2  = sm + OFF_B2;
    float* sW3  = sm + OFF_W3;

    const int t = threadIdx.x;
    const int lane = t & 31;
    const int w = t >> 5;
    const int g = w >> 3;          // group 0/1
    const int wg = w & 7;          // warp in group
    const int mg = wg & 1;         // rows mg*32 .. +31
    const int ng = wg >> 1;        // L1: cols ng*64..; L2: cols ng*32..
    const int tg = t & 255;        // thread in group

    float* GB = sm + OFF_G0 + g * GSTRIDE;
    uint4*    sAfq  = (uint4*)(GB + GOFF_AF);     // [2][512] uint4
    uint32_t* sH1f  = (uint32_t*)(GB + GOFF_H1F); // 2048 uint4
    float*    sHS   = GB + GOFF_HS;               // [2][512]
    float*    sOutP = GB + GOFF_OUT;              // [2][64*4]

    // ---- build W2 frags: [ng(4)][ks(16)][np(2)][lane(32)] uint4 ----
    for (int i = t; i < 16384; i += 512) {
        int ws = i & 3, ln = (i >> 2) & 31;
        int np = (i >> 7) & 1, ks = (i >> 8) & 15, gg = (i >> 12) & 3;
        int krow = ks * 16 + (ws & 1) * 8 + (ln & 3) * 2;
        int col  = gg * 32 + np * 16 + (ws >> 1) * 8 + (ln >> 2);
        sW2f[i] = pk(W2[krow * HID2 + col], W2[(krow + 1) * HID2 + col]);
    }
    // ---- build W1a frags: [ng(4)][ks(4)][np(4)][lane(32)] uint4 ----
    for (int i = t; i < 8192; i += 512) {
        int ws = i & 3, ln = (i >> 2) & 31;
        int np = (i >> 7) & 3, ks = (i >> 9) & 3, gg = (i >> 11) & 3;
        int krow = STATE_DIM + ks * 16 + (ws & 1) * 8 + (ln & 3) * 2;
        int col  = gg * 64 + np * 16 + (ws >> 1) * 8 + (ln >> 2);
        sW1f[i] = pk(W1[krow * HID + col], W1[(krow + 1) * HID + col]);
    }
    if (t < 128) { sB2[t] = b2[t]; sW3[t] = W3[t]; }

    // ---- af staging ----
    const int s_rowoff = (lane >> 2);
    const int s_coloff = (lane & 3) * 2;

    auto load_af = [&](int tl, uint32_t* pp) {
#pragma unroll
        for (int j = 0; j < 2; j++) {
            int idx = tg + j * 256;
            int rg16 = idx >> 7, ks = (idx >> 5) & 3;
            const float* base = af + (size_t)(tl * TILE_M + rg16 * 16 + s_rowoff) * AFEAT
                                   + ks * 16 + s_coloff;
            float2 v0 = *(const float2*)(base);
            float2 v1 = *(const float2*)(base + 8 * AFEAT);
            float2 v2 = *(const float2*)(base + 8);
            float2 v3 = *(const float2*)(base + 8 * AFEAT + 8);
            pp[j * 4 + 0] = pk(v0.x, v0.y);
            pp[j * 4 + 1] = pk(v1.x, v1.y);
            pp[j * 4 + 2] = pk(v2.x, v2.y);
            pp[j * 4 + 3] = pk(v3.x, v3.y);
        }
    };
    auto store_af = [&](const uint32_t* pp, int buf) {
#pragma unroll
        for (int j = 0; j < 2; j++)
            sAfq[buf * 512 + tg + j * 256] =
                make_uint4(pp[j * 4 + 0], pp[j * 4 + 1], pp[j * 4 + 2], pp[j * 4 + 3]);
    };
    auto stage_hs = [&](int tl, int buf) {
        int r0 = tl * TILE_M;
        int blo = r0 / KACT;
        int bhi = (r0 + TILE_M - 1) / KACT;
        sHS[buf * 512 + tg]       = g_hstate[blo * HID + tg];
        sHS[buf * 512 + 256 + tg] = g_hstate[bhi * HID + tg];
    };

    __syncthreads();               // weights ready (both groups)

    const int G = gridDim.x;
    const int tstep = 2 * G;
    int tile = blockIdx.x * 2 + g;

    // ---- prologue ----
    {
        uint32_t pp[8];
        load_af(tile, pp);
        store_af(pp, 0);
        stage_hs(tile, 0);
    }
    GBAR(g);

    const float bias3 = __ldg(b3);
    const uint4* w1v = (const uint4*)sW1f;
    const uint4* w2v = (const uint4*)sW2f;
    const uint4* h1v = (const uint4*)sH1f;

    int it = 0;
    for (; tile < NTILES; tile += tstep, it++) {
        const int row0 = tile * TILE_M;
        const int ntile = tile + tstep;
        const int cur = it & 1, nxt = cur ^ 1;
        const int split = (row0 / KACT + 1) * KACT - row0;

        // ---- write out(tile - tstep): reduce ng-slots from sOutP[nxt] ----
        if (it >= 1 && tg < 64) {
            float4 v = *(float4*)(sOutP + nxt * 256 + tg * 4);
            out[row0 - tstep * TILE_M + tg] = v.x + v.y + v.z + v.w + bias3;
        }

        // ---- prefetch next tile's af ----
        uint32_t pp[8];
        if (ntile < NTILES) load_af(ntile, pp);

        // ---- L1: C = af @ W1a, init C = h_state (exact fp32) ----
        // C-frag: bit0 = col parity, bit1 = row+8. Vectorized init:
        // col pair (c, c+1) = one float2; batch select hoisted per (mf, row-bit).
        float acc[2][8][4];
        const float2* hsc2 = (const float2*)(sHS + cur * 512);
        const int c2base = (ng * 64 + 2 * (lane & 3)) >> 1;
#pragma unroll
        for (int mf = 0; mf < 2; mf++) {
            const int r = mg * 32 + mf * 16 + (lane >> 2);
            const int selA = (r >= split) ? 128 : 0;        // +256 floats = +128 float2
            const int selB = (r + 8 >= split) ? 128 : 0;
#pragma unroll
            for (int nt = 0; nt < 8; nt++) {
                int c2 = c2base + nt * 4;
                float2 va = hsc2[selA + c2];
                float2 vb = hsc2[selB + c2];
                acc[mf][nt][0] = va.x; acc[mf][nt][1] = va.y;
                acc[mf][nt][2] = vb.x; acc[mf][nt][3] = vb.y;
            }
        }
#pragma unroll
        for (int ks = 0; ks < 4; ks++) {
            uint4 a0 = sAfq[cur * 512 + ((mg * 2 + 0) * 4 + ks) * 32 + lane];
            uint4 a1 = sAfq[cur * 512 + ((mg * 2 + 1) * 4 + ks) * 32 + lane];
#pragma unroll
            for (int np = 0; np < 4; np++) {
                uint4 b = w1v[((ng * 4 + ks) * 4 + np) * 32 + lane];
                mma16(acc[0][np * 2],     a0, b.x, b.y);
                mma16(acc[0][np * 2 + 1], a0, b.z, b.w);
                mma16(acc[1][np * 2],     a1, b.x, b.y);
                mma16(acc[1][np * 2 + 1], a1, b.z, b.w);
            }
        }
        // ---- ep1: relu -> f16 pairs -> sH1f as L2 A-frags ----
#pragma unroll
        for (int mf = 0; mf < 2; mf++)
#pragma unroll
        for (int q = 0; q < 4; q++) {
            uint4 v;
            v.x = pkr(acc[mf][2 * q][0],     acc[mf][2 * q][1]);
            v.y = pkr(acc[mf][2 * q][2],     acc[mf][2 * q][3]);
            v.z = pkr(acc[mf][2 * q + 1][0], acc[mf][2 * q + 1][1]);
            v.w = pkr(acc[mf][2 * q + 1][2], acc[mf][2 * q + 1][3]);
            ((uint4*)sH1f)[((mg * 2 + mf) * 16 + ng * 4 + q) * 32 + lane] = v;
        }
        GBAR(g);   // S1: h1 ready, prev-buffer reads all done

        // ---- stage next tile while L2 runs ----
        if (ntile < NTILES) {
            store_af(pp, nxt);
            stage_hs(ntile, nxt);
        }

        // ---- L2: C2 = h1 @ W2 ----
        float acc2[2][4][4];
#pragma unroll
        for (int mf = 0; mf < 2; mf++)
#pragma unroll
        for (int nt = 0; nt < 4; nt++)
#pragma unroll
        for (int rg = 0; rg < 4; rg++) acc2[mf][nt][rg] = 0.f;
#pragma unroll
        for (int ks = 0; ks < 16; ks++) {
            uint4 a0 = h1v[((mg * 2 + 0) * 16 + ks) * 32 + lane];
            uint4 a1 = h1v[((mg * 2 + 1) * 16 + ks) * 32 + lane];
#pragma unroll
            for (int np = 0; np < 2; np++) {
                uint4 b = w2v[((ng * 16 + ks) * 2 + np) * 32 + lane];
                mma16(acc2[0][np * 2],     a0, b.x, b.y);
                mma16(acc2[0][np * 2 + 1], a0, b.z, b.w);
                mma16(acc2[1][np * 2],     a1, b.x, b.y);
                mma16(acc2[1][np * 2 + 1], a1, b.z, b.w);
            }
        }

        // ---- L3: relu(C2 + b2) . W3 partials -> sOutP[cur][row][ng] ----
#pragma unroll
        for (int mf = 0; mf < 2; mf++) {
            float part[2] = {0.f, 0.f};
#pragma unroll
            for (int nt = 0; nt < 4; nt++)
#pragma unroll
            for (int rg = 0; rg < 4; rg++) {
                int c = ng * 32 + nt * 8 + 2 * (lane & 3) + (rg & 1);
                float v = fmaxf(acc2[mf][nt][rg] + sB2[c], 0.f);
                part[rg >> 1] += v * sW3[c];
            }
#pragma unroll
            for (int rb = 0; rb < 2; rb++) {
                float v = part[rb];
                v += __shfl_xor_sync(0xffffffffu, v, 1);
                v += __shfl_xor_sync(0xffffffffu, v, 2);
                if ((lane & 3) == 0)
                    sOutP[cur * 256 + (mg * 32 + mf * 16 + rb * 8 + (lane >> 2)) * 4 + ng] = v;
            }
        }
        GBAR(g);   // S2: L3 stores + h1 reads done; buffers flip
    }

    // ---- drain: write the final tile's output ----
    if (it >= 1 && tg < 64) {
        const int last = tile - tstep;
        float4 v = *(float4*)(sOutP + ((it - 1) & 1) * 256 + tg * 4);
        out[last * TILE_M + tg] = v.x + v.y + v.z + v.w + bias3;
    }
}

// ---------------------------------------------------------------------------
extern "C" void kernel_launch(void* const* d_in, const int* in_sizes, int n_in,
                              void* d_out, int out_size)
{
    const float* state = (const float*)d_in[0];
    const float* afeats = (const float*)d_in[1];
    const float* W1    = (const float*)d_in[2];
    const float* b1    = (const float*)d_in[3];
    const float* W2    = (const float*)d_in[4];
    const float* b2    = (const float*)d_in[5];
    const float* W3    = (const float*)d_in[6];
    const float* b3    = (const float*)d_in[7];
    float* out = (float*)d_out;
    (void)in_sizes; (void)n_in; (void)out_size;

    static int sm_count = 0;
    if (sm_count == 0) {
        cudaDeviceGetAttribute(&sm_count, cudaDevAttrMultiProcessorCount, 0);
        if (sm_count <= 0) sm_count = 148;
        cudaFuncSetAttribute(actor_main,
                             cudaFuncAttributeMaxDynamicSharedMemorySize, SMEM_BYTES);
    }

    hstate_kernel<<<128, 256>>>(state, W1, b1);
    actor_main<<<sm_count, 512, SMEM_BYTES>>>(afeats, W1, W2, b2, W3, b3, out);
}